// round 10
// baseline (speedup 1.0000x reference)
#include <cuda_runtime.h>
#include <cstdint>
#include <math.h>

#define NB 8192
#define ND 1024
#define BM 128
#define BN 128
#define BKB 128                          /* K bytes (int8 elems) per k-block */
#define NBLK (NB / BM)                   /* 64 row/col blocks */
#define NTILES (NBLK * (NBLK + 1) / 2)   /* 2080 upper-tri tiles */
#define THREADS 256
#define ROWB 144                         /* padded smem row bytes */
#define KBLOCKS (ND / BKB)               /* 8 */
#define RED_BLOCKS 32

/* dynamic SMEM layout (bytes) */
#define T_BUF   (128 * ROWB)             /* 18432 */
#define OFF_SB  (2 * T_BUF)              /* 36864 */
#define OFF_RR  (4 * T_BUF)              /* 73728: s_redr [4][128] float2 */
#define OFF_RC  (OFF_RR + 4096)          /* 77824: s_redc [2][128] float2 */
#define OFF_SC  (OFF_RC + 2048)          /* 79872: row/col scales 2x128 f32 */
#define SMEM_TOTAL (OFF_SC + 1024)       /* 80896 */

// ---------------- static device scratch (no allocation) --------------------
__device__ __align__(256) signed char g_q[NB * ND];   // quantized rows (8 MB)
__device__ float  g_scale[NB];                        // per-row scale
__device__ float2 g_part[NBLK * NB];                  // [colblock][row] top-2
__device__ float2 g_red[RED_BLOCKS];

// ---------------- PTX helpers ----------------------------------------------
__device__ __forceinline__ uint32_t smem_u32(const void* p) {
    uint32_t a;
    asm("{ .reg .u64 t; cvta.to.shared.u64 t, %1; cvt.u32.u64 %0, t; }" : "=r"(a) : "l"(p));
    return a;
}
#define CP_ASYNC16(sm, gp) \
    asm volatile("cp.async.cg.shared.global [%0], [%1], 16;" :: "r"(sm), "l"(gp))
#define CP_COMMIT() asm volatile("cp.async.commit_group;" ::: "memory")
#define CP_WAIT0()  asm volatile("cp.async.wait_group 0;" ::: "memory")
#define LDMATRIX_X4(r0, r1, r2, r3, addr) \
    asm volatile("ldmatrix.sync.aligned.m8n8.x4.shared.b16 {%0,%1,%2,%3}, [%4];" \
                 : "=r"(r0), "=r"(r1), "=r"(r2), "=r"(r3) : "r"(addr))
#define MMA16832(c, a, b0, b1) \
    asm volatile("mma.sync.aligned.m16n8k32.row.col.s32.s8.s8.s32 " \
                 "{%0,%1,%2,%3},{%4,%5,%6,%7},{%8,%9},{%0,%1,%2,%3};" \
                 : "+r"((c)[0]), "+r"((c)[1]), "+r"((c)[2]), "+r"((c)[3]) \
                 : "r"((a)[0]), "r"((a)[1]), "r"((a)[2]), "r"((a)[3]), "r"(b0), "r"(b1))

__device__ __forceinline__ void top2_merge(float2& t, float2 q) {
    if (q.x > t.x) { t.y = fmaxf(t.x, q.y); t.x = q.x; }
    else           { t.y = fmaxf(t.y, q.x); }
}
__device__ __forceinline__ void top2_push(float2& t, float v) {
    if (v > t.x) { t.y = t.x; t.x = v; }
    else if (v > t.y) { t.y = v; }
}
__device__ __forceinline__ void top2_shfl_merge(float2& t, int off) {
    float2 q;
    q.x = __shfl_xor_sync(0xFFFFFFFFu, t.x, off);
    q.y = __shfl_xor_sync(0xFFFFFFFFu, t.y, off);
    top2_merge(t, q);
}

// ---------------------------------------------------------------------------
// Kernel 1: L2-normalize rows, per-row int8 quantize
// ---------------------------------------------------------------------------
__global__ void __launch_bounds__(256) normalize_quant_kernel(const float* __restrict__ x) {
    int row = blockIdx.x;
    int t = threadIdx.x;
    const float4* xr = reinterpret_cast<const float4*>(x + (size_t)row * ND);
    float4 v = xr[t];
    float s = v.x * v.x + v.y * v.y + v.z * v.z + v.w * v.w;
    float a = fmaxf(fmaxf(fabsf(v.x), fabsf(v.y)), fmaxf(fabsf(v.z), fabsf(v.w)));
    #pragma unroll
    for (int o = 16; o > 0; o >>= 1) {
        s += __shfl_xor_sync(0xFFFFFFFFu, s, o);
        a = fmaxf(a, __shfl_xor_sync(0xFFFFFFFFu, a, o));
    }
    __shared__ float ws[8], wa[8];
    int lane = t & 31, w = t >> 5;
    if (lane == 0) { ws[w] = s; wa[w] = a; }
    __syncthreads();
    if (t < 8) {
        float q = ws[t], qa = wa[t];
        #pragma unroll
        for (int o = 4; o > 0; o >>= 1) {
            q += __shfl_xor_sync(0x000000FFu, q, o);
            qa = fmaxf(qa, __shfl_xor_sync(0x000000FFu, qa, o));
        }
        if (t == 0) { ws[0] = q; wa[0] = qa; }
    }
    __syncthreads();
    float inv = 1.0f / fmaxf(sqrtf(ws[0]), 1e-8f);
    float amax = fmaxf(wa[0] * inv, 1e-12f);   // max |normalized element|
    float qscl = 127.0f / amax;                // x_hat -> int
    if (t == 0) g_scale[row] = amax * (1.0f / 127.0f);

    char4 qv;
    qv.x = (signed char)__float2int_rn(v.x * inv * qscl);
    qv.y = (signed char)__float2int_rn(v.y * inv * qscl);
    qv.z = (signed char)__float2int_rn(v.z * inv * qscl);
    qv.w = (signed char)__float2int_rn(v.w * inv * qscl);
    reinterpret_cast<char4*>(g_q + (size_t)row * ND)[t] = qv;
}

// ---------------------------------------------------------------------------
// Kernel 2: symmetric int8 mma.sync — one upper-triangle 128x128 tile per CTA
// ---------------------------------------------------------------------------
__global__ void __launch_bounds__(THREADS, 2) top2_sym_kernel() {
    extern __shared__ char smem[];
    float2* s_redr = reinterpret_cast<float2*>(smem + OFF_RR);  // [4][128]
    float2* s_redc = reinterpret_cast<float2*>(smem + OFF_RC);  // [2][128]
    float*  s_rsc  = reinterpret_cast<float*>(smem + OFF_SC);   // [128]
    float*  s_csc  = s_rsc + 128;                               // [128]

    // decode upper-triangle (i, j), i <= j
    int i = 0, base = 0;
    {
        const int idx = blockIdx.x;
        while (base + (NBLK - i) <= idx) { base += NBLK - i; ++i; }
        base = idx - base;
    }
    const int j = i + base;
    const int rowStart = i * BM;
    const int colStart = j * BN;

    const int tid = threadIdx.x;
    const int wid = tid >> 5, lane = tid & 31;
    const int warpM = wid >> 2, warpN = wid & 3;   // 2 x 4 warp grid (64x32)

    const uint32_t sAu = smem_u32(smem);
    const uint32_t sBu = smem_u32(smem + OFF_SB);

    // stage per-row/col scales (consumed in epilogue; syncs intervene)
    if (tid < 128) s_rsc[tid] = g_scale[rowStart + tid];
    else           s_csc[tid - 128] = g_scale[colStart + tid - 128];

    // ldmatrix x4 lane addressing (group g = lane>>3, lr = lane&7)
    const int lr = lane & 7, lg = lane >> 3;
    const uint32_t a_off = (uint32_t)((warpM * 64 + lr + (lg & 1) * 8) * ROWB + (lg >> 1) * 16);
    const uint32_t b_off = (uint32_t)((warpN * 32 + lr + (lg >> 1) * 8) * ROWB + (lg & 1) * 16);

    // cp.async decomposition: idx = tid + q*256 -> row = idx>>3, 16B chunk = idx&7
    int32_t acc[4][4][4];
    #pragma unroll
    for (int mi = 0; mi < 4; mi++)
        #pragma unroll
        for (int nj = 0; nj < 4; nj++)
            #pragma unroll
            for (int e = 0; e < 4; e++) acc[mi][nj][e] = 0;

    // ---- prologue: stage 0 ----
    #pragma unroll
    for (int q = 0; q < 4; q++) {
        int idx = tid + q * 256;
        int r = idx >> 3, ch = idx & 7;
        uint32_t so = (uint32_t)(r * ROWB + ch * 16);
        CP_ASYNC16(sAu + so, g_q + (size_t)(rowStart + r) * ND + ch * 16);
        CP_ASYNC16(sBu + so, g_q + (size_t)(colStart + r) * ND + ch * 16);
    }
    CP_COMMIT();

    for (int kb = 0; kb < KBLOCKS; kb++) {
        CP_WAIT0();
        __syncthreads();

        if (kb + 1 < KBLOCKS) {
            const int k0 = (kb + 1) * BKB;
            const uint32_t bo = ((kb + 1) & 1) * T_BUF;
            #pragma unroll
            for (int q = 0; q < 4; q++) {
                int idx = tid + q * 256;
                int r = idx >> 3, ch = idx & 7;
                uint32_t so = bo + (uint32_t)(r * ROWB + ch * 16);
                CP_ASYNC16(sAu + so, g_q + (size_t)(rowStart + r) * ND + k0 + ch * 16);
                CP_ASYNC16(sBu + so, g_q + (size_t)(colStart + r) * ND + k0 + ch * 16);
            }
            CP_COMMIT();
        }

        const uint32_t bo = (kb & 1) * T_BUF;
        #pragma unroll
        for (int ks = 0; ks < 4; ks++) {          // 4 x k32 per 128B block
            uint32_t af[4][4];
            #pragma unroll
            for (int mi = 0; mi < 4; mi++) {
                uint32_t addr = sAu + bo + ks * 32 + a_off + mi * (16 * ROWB);
                LDMATRIX_X4(af[mi][0], af[mi][1], af[mi][2], af[mi][3], addr);
            }
            uint32_t bf[2][4];
            #pragma unroll
            for (int nb = 0; nb < 2; nb++) {
                uint32_t addr = sBu + bo + ks * 32 + b_off + nb * (16 * ROWB);
                LDMATRIX_X4(bf[nb][0], bf[nb][1], bf[nb][2], bf[nb][3], addr);
            }
            #pragma unroll
            for (int mi = 0; mi < 4; mi++)
                #pragma unroll
                for (int nj = 0; nj < 4; nj++)
                    MMA16832(acc[mi][nj], af[mi],
                             bf[nj >> 1][(nj & 1) * 2], bf[nj >> 1][(nj & 1) * 2 + 1]);
        }
    }

    // ---- mask diagonal in-place (INT_MIN -> hugely negative after scaling) ----
    #pragma unroll
    for (int mi = 0; mi < 4; mi++) {
        const int row0 = rowStart + warpM * 64 + mi * 16 + (lane >> 2);
        #pragma unroll
        for (int nj = 0; nj < 4; nj++) {
            const int col0 = colStart + warpN * 32 + nj * 8 + (lane & 3) * 2;
            if (col0     == row0)     acc[mi][nj][0] = INT32_MIN;
            if (col0 + 1 == row0)     acc[mi][nj][1] = INT32_MIN;
            if (col0     == row0 + 8) acc[mi][nj][2] = INT32_MIN;
            if (col0 + 1 == row0 + 8) acc[mi][nj][3] = INT32_MIN;
        }
    }

    // ================= epilogue phase 1: row-side top-2 (values / s_row) ======
    {
        float2 run[8];
        #pragma unroll
        for (int t2 = 0; t2 < 8; t2++) run[t2] = make_float2(-3e7f, -3e7f);
        #pragma unroll
        for (int mi = 0; mi < 4; mi++)
            #pragma unroll
            for (int nj = 0; nj < 4; nj++) {
                const int cr = warpN * 32 + nj * 8 + (lane & 3) * 2;
                const float sc0 = s_csc[cr], sc1 = s_csc[cr + 1];
                top2_push(run[mi * 2 + 0], (float)acc[mi][nj][0] * sc0);
                top2_push(run[mi * 2 + 0], (float)acc[mi][nj][1] * sc1);
                top2_push(run[mi * 2 + 1], (float)acc[mi][nj][2] * sc0);
                top2_push(run[mi * 2 + 1], (float)acc[mi][nj][3] * sc1);
            }
        #pragma unroll
        for (int t2 = 0; t2 < 8; t2++) {
            top2_shfl_merge(run[t2], 1);
            top2_shfl_merge(run[t2], 2);
        }
        if ((lane & 3) == 0) {
            #pragma unroll
            for (int mi = 0; mi < 4; mi++) {
                int rbase = warpM * 64 + mi * 16 + (lane >> 2);
                s_redr[warpN * BM + rbase]     = run[mi * 2 + 0];
                s_redr[warpN * BM + rbase + 8] = run[mi * 2 + 1];
            }
        }
    }

    // ================= epilogue phase 2: col-side top-2 (values / s_col) ======
    if (i != j) {
        float2 crun[8];
        #pragma unroll
        for (int t2 = 0; t2 < 8; t2++) crun[t2] = make_float2(-3e7f, -3e7f);
        #pragma unroll
        for (int nj = 0; nj < 4; nj++)
            #pragma unroll
            for (int mi = 0; mi < 4; mi++) {
                const int rr = warpM * 64 + mi * 16 + (lane >> 2);
                const float sr0 = s_rsc[rr], sr8 = s_rsc[rr + 8];
                top2_push(crun[nj * 2 + 0], (float)acc[mi][nj][0] * sr0);
                top2_push(crun[nj * 2 + 1], (float)acc[mi][nj][1] * sr0);
                top2_push(crun[nj * 2 + 0], (float)acc[mi][nj][2] * sr8);
                top2_push(crun[nj * 2 + 1], (float)acc[mi][nj][3] * sr8);
            }
        #pragma unroll
        for (int t2 = 0; t2 < 8; t2++) {
            top2_shfl_merge(crun[t2], 4);
            top2_shfl_merge(crun[t2], 8);
            top2_shfl_merge(crun[t2], 16);
        }
        if (lane < 4) {
            #pragma unroll
            for (int nj = 0; nj < 4; nj++) {
                int cbase = warpN * 32 + nj * 8 + lane * 2;
                s_redc[warpM * BN + cbase]     = crun[nj * 2 + 0];
                s_redc[warpM * BN + cbase + 1] = crun[nj * 2 + 1];
            }
        }
    }
    __syncthreads();

    if (tid < BM) {
        float2 m = s_redr[tid];
        top2_merge(m, s_redr[BM + tid]);
        top2_merge(m, s_redr[2 * BM + tid]);
        top2_merge(m, s_redr[3 * BM + tid]);
        float sr = s_rsc[tid];
        m.x *= sr; m.y *= sr;
        g_part[(size_t)j * NB + rowStart + tid] = m;
    }
    if (i != j && tid >= 128) {
        int c = tid - 128;
        float2 m = s_redc[c];
        top2_merge(m, s_redc[BN + c]);
        float sc = s_csc[c];
        m.x *= sc; m.y *= sc;
        g_part[(size_t)i * NB + colStart + c] = m;
    }
}

// ---------------------------------------------------------------------------
// Kernel 3a: parallel merge of 64 partials per row + loss/gate partial sums
// ---------------------------------------------------------------------------
__global__ void __launch_bounds__(256) loss_stage1_kernel() {
    const int r = blockIdx.x * 256 + threadIdx.x;
    float2 m = g_part[r];
    #pragma unroll 8
    for (int b = 1; b < NBLK; b++) top2_merge(m, g_part[(size_t)b * NB + r]);

    float sum_lg = 0.0f, sum_g = 0.0f;
    float d2[2] = {m.x, m.y};
    #pragma unroll
    for (int e = 0; e < 2; e++) {
        float dist = sqrtf(fmaxf(2.0f - 2.0f * d2[e], 0.0f));
        float loss = -logf(dist + 1e-8f);
        float g    = 1.0f / (1.0f + expf(-(loss - 0.5f) * 10.0f));
        sum_lg += loss * g;
        sum_g  += g;
    }
    #pragma unroll
    for (int o = 16; o > 0; o >>= 1) {
        sum_lg += __shfl_xor_sync(0xFFFFFFFFu, sum_lg, o);
        sum_g  += __shfl_xor_sync(0xFFFFFFFFu, sum_g,  o);
    }
    __shared__ float s_lg[8], s_g[8];
    int lane = threadIdx.x & 31, w = threadIdx.x >> 5;
    if (lane == 0) { s_lg[w] = sum_lg; s_g[w] = sum_g; }
    __syncthreads();
    if (threadIdx.x == 0) {
        float tl = 0.0f, tg = 0.0f;
        #pragma unroll
        for (int q = 0; q < 8; q++) { tl += s_lg[q]; tg += s_g[q]; }
        g_red[blockIdx.x] = make_float2(tl, tg);
    }
}

// ---------------------------------------------------------------------------
// Kernel 3b: final scalar
// ---------------------------------------------------------------------------
__global__ void __launch_bounds__(32) loss_stage2_kernel(float* __restrict__ out) {
    const int t = threadIdx.x;
    float2 p = g_red[t];
    float tl = p.x, tg = p.y;
    #pragma unroll
    for (int o = 16; o > 0; o >>= 1) {
        tl += __shfl_xor_sync(0xFFFFFFFFu, tl, o);
        tg += __shfl_xor_sync(0xFFFFFFFFu, tg, o);
    }
    if (t == 0) {
        float weighted_mean = tl / (float)(NB * 2);
        float gated_mean    = tl / fmaxf(tg, 1.0f);
        out[0] = 0.5f * weighted_mean + 0.5f * gated_mean;
    }
}

// ---------------------------------------------------------------------------
extern "C" void kernel_launch(void* const* d_in, const int* in_sizes, int n_in,
                              void* d_out, int out_size) {
    const float* x = (const float*)d_in[0];
    float* out = (float*)d_out;

    cudaFuncSetAttribute(top2_sym_kernel,
                         cudaFuncAttributeMaxDynamicSharedMemorySize, SMEM_TOTAL);

    normalize_quant_kernel<<<NB, 256>>>(x);
    top2_sym_kernel<<<NTILES, THREADS, SMEM_TOTAL>>>();
    loss_stage1_kernel<<<RED_BLOCKS, 256>>>();
    loss_stage2_kernel<<<1, 32>>>(out);
}

// round 11
// speedup vs baseline: 2.1796x; 2.1796x over previous
#include <cuda_runtime.h>
#include <cuda_fp16.h>
#include <cstdint>
#include <math.h>

#define NB 8192
#define ND 1024
#define BM 128
#define BN 128
#define BK 64
#define NBLK (NB / BM)                   /* 64 row/col blocks */
#define NTILES (NBLK * (NBLK + 1) / 2)   /* 2080 upper-tri tiles */
#define THREADS 256
#define LDS_PAD 72                       /* halves per smem row (144B stride) */
#define KBLOCKS (ND / BK)                /* 16 */
#define RED_BLOCKS 32

/* dynamic SMEM layout (bytes) */
#define T_BUF   18432                    /* 128 * 72 * 2 */
#define OFF_SB  (2 * T_BUF)
#define OFF_RR  (4 * T_BUF)              /* s_redr [4][128] float2 */
#define OFF_RC  (OFF_RR + 4096)          /* s_redc [2][128] float2 */
#define SMEM_TOTAL (OFF_RC + 2048)       /* 79872 B */

// ---------------- static device scratch (no allocation) --------------------
__device__ __half g_h[NB * ND];             // normalized rows fp16 (16 MB)
__device__ float2 g_part[NBLK * NB];        // [colblock][row] top-2 (4 MB)
__device__ float2 g_red[RED_BLOCKS];

// ---------------- PTX helpers ----------------------------------------------
__device__ __forceinline__ uint32_t smem_u32(const void* p) {
    uint32_t a;
    asm("{ .reg .u64 t; cvta.to.shared.u64 t, %1; cvt.u32.u64 %0, t; }" : "=r"(a) : "l"(p));
    return a;
}
#define CP_ASYNC16(sm, gp) \
    asm volatile("cp.async.cg.shared.global [%0], [%1], 16;" :: "r"(sm), "l"(gp))
#define CP_COMMIT() asm volatile("cp.async.commit_group;" ::: "memory")
#define CP_WAIT0()  asm volatile("cp.async.wait_group 0;" ::: "memory")
#define LDMATRIX_X4(r0, r1, r2, r3, addr) \
    asm volatile("ldmatrix.sync.aligned.m8n8.x4.shared.b16 {%0,%1,%2,%3}, [%4];" \
                 : "=r"(r0), "=r"(r1), "=r"(r2), "=r"(r3) : "r"(addr))
/* f16-accumulator HMMA: D(f16x2 x2) = A*B + D */
#define MMA16816H(c, a, b0, b1) \
    asm volatile("mma.sync.aligned.m16n8k16.row.col.f16.f16.f16.f16 " \
                 "{%0,%1},{%2,%3,%4,%5},{%6,%7},{%0,%1};" \
                 : "+r"((c)[0]), "+r"((c)[1]) \
                 : "r"((a)[0]), "r"((a)[1]), "r"((a)[2]), "r"((a)[3]), "r"(b0), "r"(b1))

__device__ __forceinline__ void top2_merge(float2& t, float2 q) {
    if (q.x > t.x) { t.y = fmaxf(t.x, q.y); t.x = q.x; }
    else           { t.y = fmaxf(t.y, q.x); }
}
__device__ __forceinline__ void top2_push(float2& t, float v) {
    if (v > t.x) { t.y = t.x; t.x = v; }
    else if (v > t.y) { t.y = v; }
}
__device__ __forceinline__ void top2_shfl_merge(float2& t, int off) {
    float2 q;
    q.x = __shfl_xor_sync(0xFFFFFFFFu, t.x, off);
    q.y = __shfl_xor_sync(0xFFFFFFFFu, t.y, off);
    top2_merge(t, q);
}

// ---------------------------------------------------------------------------
// Kernel 1: L2-normalize rows, store fp16
// ---------------------------------------------------------------------------
__global__ void __launch_bounds__(256) normalize_kernel(const float* __restrict__ x) {
    int row = blockIdx.x;
    int t = threadIdx.x;
    const float4* xr = reinterpret_cast<const float4*>(x + (size_t)row * ND);
    float4 v = xr[t];
    float s = v.x * v.x + v.y * v.y + v.z * v.z + v.w * v.w;
    #pragma unroll
    for (int o = 16; o > 0; o >>= 1) s += __shfl_xor_sync(0xFFFFFFFFu, s, o);
    __shared__ float ws[8];
    int lane = t & 31, w = t >> 5;
    if (lane == 0) ws[w] = s;
    __syncthreads();
    if (t < 8) {
        float q = ws[t];
        #pragma unroll
        for (int o = 4; o > 0; o >>= 1) q += __shfl_xor_sync(0x000000FFu, q, o);
        if (t == 0) ws[0] = q;
    }
    __syncthreads();
    float inv = 1.0f / fmaxf(sqrtf(ws[0]), 1e-8f);
    __half2* oh = reinterpret_cast<__half2*>(g_h + (size_t)row * ND);
    oh[t * 2 + 0] = __floats2half2_rn(v.x * inv, v.y * inv);
    oh[t * 2 + 1] = __floats2half2_rn(v.z * inv, v.w * inv);
}

// ---------------------------------------------------------------------------
// Kernel 2: symmetric fp16 mma.sync (f16 accumulators) — one upper-tri tile
//           per CTA, BK=64, single __syncthreads per k-block.
// ---------------------------------------------------------------------------
__global__ void __launch_bounds__(THREADS, 2) top2_sym_kernel() {
    extern __shared__ char smem[];
    float2* s_redr = reinterpret_cast<float2*>(smem + OFF_RR);  // [4][128]
    float2* s_redc = reinterpret_cast<float2*>(smem + OFF_RC);  // [2][128]

    // decode upper-triangle (i, j), i <= j
    int i = 0, base = 0;
    {
        const int idx = blockIdx.x;
        while (base + (NBLK - i) <= idx) { base += NBLK - i; ++i; }
        base = idx - base;
    }
    const int j = i + base;
    const int rowStart = i * BM;
    const int colStart = j * BN;

    const int tid = threadIdx.x;
    const int wid = tid >> 5, lane = tid & 31;
    const int warpM = wid >> 2, warpN = wid & 3;   // 2 x 4 warp grid (64x32)

    const uint32_t sAu = smem_u32(smem);
    const uint32_t sBu = smem_u32(smem + OFF_SB);

    const int a_r = lane & 15;
    const int a_k = (lane >> 4) << 3;
    const int b_n = (lane & 7) + ((lane >> 4) << 3);
    const int b_k = ((lane >> 3) & 1) << 3;

    const int l_r = tid >> 3, l_k = tid & 7;
    const uint32_t st_base = (uint32_t)(l_r * LDS_PAD + l_k * 8) * 2;

    uint32_t hacc[4][4][2];        // f16x2 accumulators
    #pragma unroll
    for (int mi = 0; mi < 4; mi++)
        #pragma unroll
        for (int nj = 0; nj < 4; nj++) { hacc[mi][nj][0] = 0u; hacc[mi][nj][1] = 0u; }

    // ---- prologue: stage 0 (k0 = 0) ----
    #pragma unroll
    for (int q = 0; q < 4; q++) {
        const uint32_t so = st_base + q * 32 * LDS_PAD * 2;
        const size_t go = (size_t)(q * 32) * ND;
        CP_ASYNC16(sAu + so, g_h + (size_t)(rowStart + l_r) * ND + go + l_k * 8);
        CP_ASYNC16(sBu + so, g_h + (size_t)(colStart + l_r) * ND + go + l_k * 8);
    }
    CP_COMMIT();

    for (int kb = 0; kb < KBLOCKS; kb++) {
        CP_WAIT0();
        __syncthreads();   // data kb visible AND compute kb-1 finished

        if (kb + 1 < KBLOCKS) {
            const int k0 = (kb + 1) * BK;
            const uint32_t bo = ((kb + 1) & 1) * T_BUF;
            #pragma unroll
            for (int q = 0; q < 4; q++) {
                const uint32_t so = bo + st_base + q * 32 * LDS_PAD * 2;
                const size_t go = (size_t)(q * 32) * ND + k0;
                CP_ASYNC16(sAu + so, g_h + (size_t)(rowStart + l_r) * ND + go + l_k * 8);
                CP_ASYNC16(sBu + so, g_h + (size_t)(colStart + l_r) * ND + go + l_k * 8);
            }
            CP_COMMIT();
        }

        const uint32_t bo = (kb & 1) * T_BUF;
        #pragma unroll
        for (int ks = 0; ks < 4; ks++) {
            uint32_t af[4][4];
            #pragma unroll
            for (int mi = 0; mi < 4; mi++) {
                uint32_t addr = sAu + bo +
                    ((warpM * 64 + mi * 16 + a_r) * LDS_PAD + ks * 16 + a_k) * 2;
                LDMATRIX_X4(af[mi][0], af[mi][1], af[mi][2], af[mi][3], addr);
            }
            uint32_t bf[2][4];
            #pragma unroll
            for (int nb = 0; nb < 2; nb++) {
                uint32_t addr = sBu + bo +
                    ((warpN * 32 + nb * 16 + b_n) * LDS_PAD + ks * 16 + b_k) * 2;
                LDMATRIX_X4(bf[nb][0], bf[nb][1], bf[nb][2], bf[nb][3], addr);
            }
            #pragma unroll
            for (int mi = 0; mi < 4; mi++)
                #pragma unroll
                for (int nj = 0; nj < 4; nj++)
                    MMA16816H(hacc[mi][nj], af[mi],
                              bf[nj >> 1][(nj & 1) * 2], bf[nj >> 1][(nj & 1) * 2 + 1]);
        }
    }

    // ---- unpack f16 accumulators to fp32 ----
    float acc[4][4][4];
    #pragma unroll
    for (int mi = 0; mi < 4; mi++)
        #pragma unroll
        for (int nj = 0; nj < 4; nj++) {
            float2 f0 = __half22float2(*reinterpret_cast<__half2*>(&hacc[mi][nj][0]));
            float2 f1 = __half22float2(*reinterpret_cast<__half2*>(&hacc[mi][nj][1]));
            acc[mi][nj][0] = f0.x; acc[mi][nj][1] = f0.y;
            acc[mi][nj][2] = f1.x; acc[mi][nj][3] = f1.y;
        }

    // ---- mask diagonal in-place ----
    #pragma unroll
    for (int mi = 0; mi < 4; mi++) {
        const int row0 = rowStart + warpM * 64 + mi * 16 + (lane >> 2);
        #pragma unroll
        for (int nj = 0; nj < 4; nj++) {
            const int col0 = colStart + warpN * 32 + nj * 8 + (lane & 3) * 2;
            if (col0     == row0)     acc[mi][nj][0] = -2.0f;
            if (col0 + 1 == row0)     acc[mi][nj][1] = -2.0f;
            if (col0     == row0 + 8) acc[mi][nj][2] = -2.0f;
            if (col0 + 1 == row0 + 8) acc[mi][nj][3] = -2.0f;
        }
    }

    // ================= epilogue phase 1: row-side top-2 =================
    {
        float2 run[8];
        #pragma unroll
        for (int t2 = 0; t2 < 8; t2++) run[t2] = make_float2(-2.0f, -2.0f);
        #pragma unroll
        for (int mi = 0; mi < 4; mi++)
            #pragma unroll
            for (int nj = 0; nj < 4; nj++) {
                top2_push(run[mi * 2 + 0], acc[mi][nj][0]);
                top2_push(run[mi * 2 + 0], acc[mi][nj][1]);
                top2_push(run[mi * 2 + 1], acc[mi][nj][2]);
                top2_push(run[mi * 2 + 1], acc[mi][nj][3]);
            }
        #pragma unroll
        for (int t2 = 0; t2 < 8; t2++) {
            top2_shfl_merge(run[t2], 1);
            top2_shfl_merge(run[t2], 2);
        }
        if ((lane & 3) == 0) {
            #pragma unroll
            for (int mi = 0; mi < 4; mi++) {
                int rbase = warpM * 64 + mi * 16 + (lane >> 2);
                s_redr[warpN * BM + rbase]     = run[mi * 2 + 0];
                s_redr[warpN * BM + rbase + 8] = run[mi * 2 + 1];
            }
        }
    }

    // ================= epilogue phase 2: col-side top-2 =================
    if (i != j) {
        float2 crun[8];
        #pragma unroll
        for (int t2 = 0; t2 < 8; t2++) crun[t2] = make_float2(-2.0f, -2.0f);
        #pragma unroll
        for (int nj = 0; nj < 4; nj++)
            #pragma unroll
            for (int mi = 0; mi < 4; mi++) {
                top2_push(crun[nj * 2 + 0], acc[mi][nj][0]);
                top2_push(crun[nj * 2 + 1], acc[mi][nj][1]);
                top2_push(crun[nj * 2 + 0], acc[mi][nj][2]);
                top2_push(crun[nj * 2 + 1], acc[mi][nj][3]);
            }
        #pragma unroll
        for (int t2 = 0; t2 < 8; t2++) {
            top2_shfl_merge(crun[t2], 4);
            top2_shfl_merge(crun[t2], 8);
            top2_shfl_merge(crun[t2], 16);
        }
        if (lane < 4) {
            #pragma unroll
            for (int nj = 0; nj < 4; nj++) {
                int cbase = warpN * 32 + nj * 8 + lane * 2;
                s_redc[warpM * BN + cbase]     = crun[nj * 2 + 0];
                s_redc[warpM * BN + cbase + 1] = crun[nj * 2 + 1];
            }
        }
    }
    __syncthreads();

    // [blk][row] layout: coalesced writes
    if (tid < BM) {
        float2 m = s_redr[tid];
        top2_merge(m, s_redr[BM + tid]);
        top2_merge(m, s_redr[2 * BM + tid]);
        top2_merge(m, s_redr[3 * BM + tid]);
        g_part[(size_t)j * NB + rowStart + tid] = m;
    }
    if (i != j && tid >= 128) {
        int c = tid - 128;
        float2 m = s_redc[c];
        top2_merge(m, s_redc[BN + c]);
        g_part[(size_t)i * NB + colStart + c] = m;
    }
}

// ---------------------------------------------------------------------------
// Kernel 3a: parallel merge of 64 partials per row + loss/gate partial sums
// ---------------------------------------------------------------------------
__global__ void __launch_bounds__(256) loss_stage1_kernel() {
    const int r = blockIdx.x * 256 + threadIdx.x;
    float2 m = g_part[r];
    #pragma unroll 8
    for (int b = 1; b < NBLK; b++) top2_merge(m, g_part[(size_t)b * NB + r]);

    float sum_lg = 0.0f, sum_g = 0.0f;
    float d2[2] = {m.x, m.y};
    #pragma unroll
    for (int e = 0; e < 2; e++) {
        float dist = sqrtf(fmaxf(2.0f - 2.0f * d2[e], 0.0f));
        float loss = -logf(dist + 1e-8f);
        float g    = 1.0f / (1.0f + expf(-(loss - 0.5f) * 10.0f));
        sum_lg += loss * g;
        sum_g  += g;
    }
    #pragma unroll
    for (int o = 16; o > 0; o >>= 1) {
        sum_lg += __shfl_xor_sync(0xFFFFFFFFu, sum_lg, o);
        sum_g  += __shfl_xor_sync(0xFFFFFFFFu, sum_g,  o);
    }
    __shared__ float s_lg[8], s_g[8];
    int lane = threadIdx.x & 31, w = threadIdx.x >> 5;
    if (lane == 0) { s_lg[w] = sum_lg; s_g[w] = sum_g; }
    __syncthreads();
    if (threadIdx.x == 0) {
        float tl = 0.0f, tg = 0.0f;
        #pragma unroll
        for (int q = 0; q < 8; q++) { tl += s_lg[q]; tg += s_g[q]; }
        g_red[blockIdx.x] = make_float2(tl, tg);
    }
}

// ---------------------------------------------------------------------------
// Kernel 3b: final scalar
// ---------------------------------------------------------------------------
__global__ void __launch_bounds__(32) loss_stage2_kernel(float* __restrict__ out) {
    const int t = threadIdx.x;
    float2 p = g_red[t];
    float tl = p.x, tg = p.y;
    #pragma unroll
    for (int o = 16; o > 0; o >>= 1) {
        tl += __shfl_xor_sync(0xFFFFFFFFu, tl, o);
        tg += __shfl_xor_sync(0xFFFFFFFFu, tg, o);
    }
    if (t == 0) {
        float weighted_mean = tl / (float)(NB * 2);
        float gated_mean    = tl / fmaxf(tg, 1.0f);
        out[0] = 0.5f * weighted_mean + 0.5f * gated_mean;
    }
}

// ---------------------------------------------------------------------------
extern "C" void kernel_launch(void* const* d_in, const int* in_sizes, int n_in,
                              void* d_out, int out_size) {
    const float* x = (const float*)d_in[0];
    float* out = (float*)d_out;

    cudaFuncSetAttribute(top2_sym_kernel,
                         cudaFuncAttributeMaxDynamicSharedMemorySize, SMEM_TOTAL);

    normalize_kernel<<<NB, 256>>>(x);
    top2_sym_kernel<<<NTILES, THREADS, SMEM_TOTAL>>>();
    loss_stage1_kernel<<<RED_BLOCKS, 256>>>();
    loss_stage2_kernel<<<1, 32>>>(out);
}

// round 12
// speedup vs baseline: 2.3059x; 1.0580x over previous
#include <cuda_runtime.h>
#include <cuda_fp16.h>
#include <cstdint>
#include <math.h>

#define NB 8192
#define ND 1024
#define BM 128                  /* CTA rows */
#define BN 256                  /* CTA cols (2 x 128-col blocks) */
#define BK 64
#define NBLK 64                 /* 128-row blocks */
#define NSUPER 32               /* 256-col superblocks */
#define NCTAS 1056              /* sum_{i=0}^{63} (32 - i/2) */
#define THREADS 256
#define LDS_PAD 72              /* halves per smem row (144B) */
#define KBLOCKS (ND / BK)       /* 16 */
#define RED_BLOCKS 32

/* dynamic SMEM layout (bytes) */
#define A_BUF 18432             /* 128*144 */
#define B_BUF 36864             /* 256*144 */
#define OFF_B (2 * A_BUF)       /* 36864 */
#define SMEM_TOTAL (OFF_B + 2 * B_BUF)   /* 110592 */
/* epilogue scratch aliases A stage-0 (dead after kb=14) */
#define OFF_RR 0                /* s_redr [4][128] float2 = 4096 B */
#define OFF_RC 4096             /* s_redc [2][256] float2 = 4096 B */

// ---------------- static device scratch (no allocation) --------------------
__device__ __half g_h[NB * ND];             // normalized rows fp16 (16 MB)
__device__ float2 g_part[96 * NB];          // [slot][row]; slots: 0..31 row-side (J), 32..95 col-side (i)
__device__ float2 g_red[RED_BLOCKS];

// ---------------- PTX helpers ----------------------------------------------
__device__ __forceinline__ uint32_t smem_u32(const void* p) {
    uint32_t a;
    asm("{ .reg .u64 t; cvta.to.shared.u64 t, %1; cvt.u32.u64 %0, t; }" : "=r"(a) : "l"(p));
    return a;
}
#define CP_ASYNC16(sm, gp) \
    asm volatile("cp.async.cg.shared.global [%0], [%1], 16;" :: "r"(sm), "l"(gp))
#define CP_COMMIT() asm volatile("cp.async.commit_group;" ::: "memory")
#define CP_WAIT0()  asm volatile("cp.async.wait_group 0;" ::: "memory")
#define LDMATRIX_X4(r0, r1, r2, r3, addr) \
    asm volatile("ldmatrix.sync.aligned.m8n8.x4.shared.b16 {%0,%1,%2,%3}, [%4];" \
                 : "=r"(r0), "=r"(r1), "=r"(r2), "=r"(r3) : "r"(addr))
#define MMA16816H(c, a, b0, b1) \
    asm volatile("mma.sync.aligned.m16n8k16.row.col.f16.f16.f16.f16 " \
                 "{%0,%1},{%2,%3,%4,%5},{%6,%7},{%0,%1};" \
                 : "+r"((c)[0]), "+r"((c)[1]) \
                 : "r"((a)[0]), "r"((a)[1]), "r"((a)[2]), "r"((a)[3]), "r"(b0), "r"(b1))

__device__ __forceinline__ void top2_merge(float2& t, float2 q) {
    if (q.x > t.x) { t.y = fmaxf(t.x, q.y); t.x = q.x; }
    else           { t.y = fmaxf(t.y, q.x); }
}
__device__ __forceinline__ void top2_push(float2& t, float v) {
    if (v > t.x) { t.y = t.x; t.x = v; }
    else if (v > t.y) { t.y = v; }
}
__device__ __forceinline__ void top2_shfl_merge(float2& t, int off) {
    float2 q;
    q.x = __shfl_xor_sync(0xFFFFFFFFu, t.x, off);
    q.y = __shfl_xor_sync(0xFFFFFFFFu, t.y, off);
    top2_merge(t, q);
}

// ---------------------------------------------------------------------------
// Kernel 1: L2-normalize rows, store fp16
// ---------------------------------------------------------------------------
__global__ void __launch_bounds__(256) normalize_kernel(const float* __restrict__ x) {
    int row = blockIdx.x;
    int t = threadIdx.x;
    const float4* xr = reinterpret_cast<const float4*>(x + (size_t)row * ND);
    float4 v = xr[t];
    float s = v.x * v.x + v.y * v.y + v.z * v.z + v.w * v.w;
    #pragma unroll
    for (int o = 16; o > 0; o >>= 1) s += __shfl_xor_sync(0xFFFFFFFFu, s, o);
    __shared__ float ws[8];
    int lane = t & 31, w = t >> 5;
    if (lane == 0) ws[w] = s;
    __syncthreads();
    if (t < 8) {
        float q = ws[t];
        #pragma unroll
        for (int o = 4; o > 0; o >>= 1) q += __shfl_xor_sync(0x000000FFu, q, o);
        if (t == 0) ws[0] = q;
    }
    __syncthreads();
    float inv = 1.0f / fmaxf(sqrtf(ws[0]), 1e-8f);
    __half2* oh = reinterpret_cast<__half2*>(g_h + (size_t)row * ND);
    oh[t * 2 + 0] = __floats2half2_rn(v.x * inv, v.y * inv);
    oh[t * 2 + 1] = __floats2half2_rn(v.z * inv, v.w * inv);
}

// ---------------------------------------------------------------------------
// Kernel 2: symmetric fp16 mma.sync, f16 accumulators — 128x256 tile per CTA,
//           64x64 warp tiles, BK=64, single sync per k-block.
// ---------------------------------------------------------------------------
__global__ void __launch_bounds__(THREADS, 2) top2_sym_kernel() {
    extern __shared__ char smem[];
    float2* s_redr = reinterpret_cast<float2*>(smem + OFF_RR);  // [4][128]
    float2* s_redc = reinterpret_cast<float2*>(smem + OFF_RC);  // [2][256]

    // decode (i, J): J >= i/2
    int i = 0, rem = blockIdx.x;
    while (rem >= NSUPER - (i >> 1)) { rem -= NSUPER - (i >> 1); ++i; }
    const int J = (i >> 1) + rem;
    const int rowStart = i << 7;
    const int colStart = J << 8;

    const int tid = threadIdx.x;
    const int wid = tid >> 5, lane = tid & 31;
    const int warpM = wid >> 2, warpN = wid & 3;   // 2 x 4 warps, 64x64 each

    const uint32_t sAu = smem_u32(smem);
    const uint32_t sBu = smem_u32(smem + OFF_B);

    const int a_r = lane & 15;
    const int a_k = (lane >> 4) << 3;
    const int b_n = (lane & 7) + ((lane >> 4) << 3);
    const int b_k = ((lane >> 3) & 1) << 3;

    uint32_t hacc[4][8][2];   // f16x2 accumulators (64 regs)
    #pragma unroll
    for (int mi = 0; mi < 4; mi++)
        #pragma unroll
        for (int nj = 0; nj < 8; nj++) { hacc[mi][nj][0] = 0u; hacc[mi][nj][1] = 0u; }

    // ---- prologue: stage 0 ----
    #pragma unroll
    for (int q = 0; q < 4; q++) {
        int idx = tid + q * 256, r = idx >> 3, ch = idx & 7;
        CP_ASYNC16(sAu + (uint32_t)(r * LDS_PAD * 2 + ch * 16),
                   g_h + (size_t)(rowStart + r) * ND + ch * 8);
    }
    #pragma unroll
    for (int q = 0; q < 8; q++) {
        int idx = tid + q * 256, r = idx >> 3, ch = idx & 7;
        CP_ASYNC16(sBu + (uint32_t)(r * LDS_PAD * 2 + ch * 16),
                   g_h + (size_t)(colStart + r) * ND + ch * 8);
    }
    CP_COMMIT();

    for (int kb = 0; kb < KBLOCKS; kb++) {
        CP_WAIT0();
        __syncthreads();

        if (kb + 1 < KBLOCKS) {
            const int k0 = (kb + 1) * BK;
            const uint32_t boA = ((kb + 1) & 1) * A_BUF;
            const uint32_t boB = ((kb + 1) & 1) * B_BUF;
            #pragma unroll
            for (int q = 0; q < 4; q++) {
                int idx = tid + q * 256, r = idx >> 3, ch = idx & 7;
                CP_ASYNC16(sAu + boA + (uint32_t)(r * LDS_PAD * 2 + ch * 16),
                           g_h + (size_t)(rowStart + r) * ND + k0 + ch * 8);
            }
            #pragma unroll
            for (int q = 0; q < 8; q++) {
                int idx = tid + q * 256, r = idx >> 3, ch = idx & 7;
                CP_ASYNC16(sBu + boB + (uint32_t)(r * LDS_PAD * 2 + ch * 16),
                           g_h + (size_t)(colStart + r) * ND + k0 + ch * 8);
            }
            CP_COMMIT();
        }

        const uint32_t boA = (kb & 1) * A_BUF;
        const uint32_t boB = (kb & 1) * B_BUF;
        #pragma unroll
        for (int ks = 0; ks < 4; ks++) {
            uint32_t af[4][4];
            #pragma unroll
            for (int mi = 0; mi < 4; mi++) {
                uint32_t addr = sAu + boA +
                    ((warpM * 64 + mi * 16 + a_r) * LDS_PAD + ks * 16 + a_k) * 2;
                LDMATRIX_X4(af[mi][0], af[mi][1], af[mi][2], af[mi][3], addr);
            }
            uint32_t bf[4][4];
            #pragma unroll
            for (int nb = 0; nb < 4; nb++) {
                uint32_t addr = sBu + boB +
                    ((warpN * 64 + nb * 16 + b_n) * LDS_PAD + ks * 16 + b_k) * 2;
                LDMATRIX_X4(bf[nb][0], bf[nb][1], bf[nb][2], bf[nb][3], addr);
            }
            #pragma unroll
            for (int mi = 0; mi < 4; mi++)
                #pragma unroll
                for (int nj = 0; nj < 8; nj++)
                    MMA16816H(hacc[mi][nj], af[mi],
                              bf[nj >> 1][(nj & 1) * 2], bf[nj >> 1][(nj & 1) * 2 + 1]);
        }
    }

    // ================= epilogue phase 1: row-side top-2 =================
    // mask: col < rowStart (redundant left half) or col == row (diagonal)
    {
        float2 run[8];
        #pragma unroll
        for (int t2 = 0; t2 < 8; t2++) run[t2] = make_float2(-2.0f, -2.0f);
        #pragma unroll
        for (int mi = 0; mi < 4; mi++) {
            const int row0 = rowStart + warpM * 64 + mi * 16 + (lane >> 2);
            #pragma unroll
            for (int nj = 0; nj < 8; nj++) {
                const int col0 = colStart + warpN * 64 + nj * 8 + (lane & 3) * 2;
                float2 f0 = __half22float2(*reinterpret_cast<__half2*>(&hacc[mi][nj][0]));
                float2 f1 = __half22float2(*reinterpret_cast<__half2*>(&hacc[mi][nj][1]));
                float c0 = f0.x, c1 = f0.y, c2 = f1.x, c3 = f1.y;
                if (col0 < rowStart || col0     == row0)     c0 = -2.0f;
                if (col0 < rowStart || col0 + 1 == row0)     c1 = -2.0f;
                if (col0 < rowStart || col0     == row0 + 8) c2 = -2.0f;
                if (col0 < rowStart || col0 + 1 == row0 + 8) c3 = -2.0f;
                top2_push(run[mi * 2 + 0], c0);
                top2_push(run[mi * 2 + 0], c1);
                top2_push(run[mi * 2 + 1], c2);
                top2_push(run[mi * 2 + 1], c3);
            }
        }
        #pragma unroll
        for (int t2 = 0; t2 < 8; t2++) {
            top2_shfl_merge(run[t2], 1);
            top2_shfl_merge(run[t2], 2);
        }
        __syncthreads();   // A0 scratch now safe: every warp is past its mainloop reads
        if ((lane & 3) == 0) {
            #pragma unroll
            for (int mi = 0; mi < 4; mi++) {
                int rbase = warpM * 64 + mi * 16 + (lane >> 2);
                s_redr[warpN * BM + rbase]     = run[mi * 2 + 0];
                s_redr[warpN * BM + rbase + 8] = run[mi * 2 + 1];
            }
        }
    }

    // ================= epilogue phase 2: col-side top-2 (only c_blk > i) =====
    {
        float2 crun[16];
        #pragma unroll
        for (int t2 = 0; t2 < 16; t2++) crun[t2] = make_float2(-2.0f, -2.0f);
        #pragma unroll
        for (int nj = 0; nj < 8; nj++) {
            const int cblk = (colStart + warpN * 64 + nj * 8) >> 7;
            if (cblk > i) {
                #pragma unroll
                for (int mi = 0; mi < 4; mi++) {
                    float2 f0 = __half22float2(*reinterpret_cast<__half2*>(&hacc[mi][nj][0]));
                    float2 f1 = __half22float2(*reinterpret_cast<__half2*>(&hacc[mi][nj][1]));
                    top2_push(crun[nj * 2 + 0], f0.x);
                    top2_push(crun[nj * 2 + 1], f0.y);
                    top2_push(crun[nj * 2 + 0], f1.x);
                    top2_push(crun[nj * 2 + 1], f1.y);
                }
            }
        }
        #pragma unroll
        for (int t2 = 0; t2 < 16; t2++) {
            top2_shfl_merge(crun[t2], 4);
            top2_shfl_merge(crun[t2], 8);
            top2_shfl_merge(crun[t2], 16);
        }
        if (lane < 4) {
            #pragma unroll
            for (int nj = 0; nj < 8; nj++) {
                int cbase = warpN * 64 + nj * 8 + lane * 2;
                s_redc[warpM * BN + cbase]     = crun[nj * 2 + 0];
                s_redc[warpM * BN + cbase + 1] = crun[nj * 2 + 1];
            }
        }
    }
    __syncthreads();

    // row-side slot J; col-side slot 32 + i (coalesced [slot][row])
    if (tid < BM) {
        float2 m = s_redr[tid];
        top2_merge(m, s_redr[BM + tid]);
        top2_merge(m, s_redr[2 * BM + tid]);
        top2_merge(m, s_redr[3 * BM + tid]);
        g_part[(size_t)J * NB + rowStart + tid] = m;
    }
    {
        float2 m = s_redc[tid];
        top2_merge(m, s_redc[BN + tid]);
        g_part[(size_t)(32 + i) * NB + colStart + tid] = m;
    }
}

// ---------------------------------------------------------------------------
// Kernel 3a: per-row merge over valid slots + loss/gate partial sums
// ---------------------------------------------------------------------------
__global__ void __launch_bounds__(256) loss_stage1_kernel() {
    const int r = blockIdx.x * 256 + threadIdx.x;
    const int b = r >> 7;

    float2 m = make_float2(-2.0f, -2.0f);
    for (int Jx = b >> 1; Jx < NSUPER; Jx++) top2_merge(m, g_part[(size_t)Jx * NB + r]);
    const int imax = b | 1;
    for (int ix = 0; ix <= imax; ix++) top2_merge(m, g_part[(size_t)(32 + ix) * NB + r]);

    float sum_lg = 0.0f, sum_g = 0.0f;
    float d2[2] = {m.x, m.y};
    #pragma unroll
    for (int e = 0; e < 2; e++) {
        float dist = sqrtf(fmaxf(2.0f - 2.0f * d2[e], 0.0f));
        float loss = -logf(dist + 1e-8f);
        float g    = 1.0f / (1.0f + expf(-(loss - 0.5f) * 10.0f));
        sum_lg += loss * g;
        sum_g  += g;
    }
    #pragma unroll
    for (int o = 16; o > 0; o >>= 1) {
        sum_lg += __shfl_xor_sync(0xFFFFFFFFu, sum_lg, o);
        sum_g  += __shfl_xor_sync(0xFFFFFFFFu, sum_g,  o);
    }
    __shared__ float s_lg[8], s_g[8];
    int lane = threadIdx.x & 31, w = threadIdx.x >> 5;
    if (lane == 0) { s_lg[w] = sum_lg; s_g[w] = sum_g; }
    __syncthreads();
    if (threadIdx.x == 0) {
        float tl = 0.0f, tg = 0.0f;
        #pragma unroll
        for (int q = 0; q < 8; q++) { tl += s_lg[q]; tg += s_g[q]; }
        g_red[blockIdx.x] = make_float2(tl, tg);
    }
}

// ---------------------------------------------------------------------------
// Kernel 3b: final scalar
// ---------------------------------------------------------------------------
__global__ void __launch_bounds__(32) loss_stage2_kernel(float* __restrict__ out) {
    const int t = threadIdx.x;
    float2 p = g_red[t];
    float tl = p.x, tg = p.y;
    #pragma unroll
    for (int o = 16; o > 0; o >>= 1) {
        tl += __shfl_xor_sync(0xFFFFFFFFu, tl, o);
        tg += __shfl_xor_sync(0xFFFFFFFFu, tg, o);
    }
    if (t == 0) {
        float weighted_mean = tl / (float)(NB * 2);
        float gated_mean    = tl / fmaxf(tg, 1.0f);
        out[0] = 0.5f * weighted_mean + 0.5f * gated_mean;
    }
}

// ---------------------------------------------------------------------------
extern "C" void kernel_launch(void* const* d_in, const int* in_sizes, int n_in,
                              void* d_out, int out_size) {
    const float* x = (const float*)d_in[0];
    float* out = (float*)d_out;

    cudaFuncSetAttribute(top2_sym_kernel,
                         cudaFuncAttributeMaxDynamicSharedMemorySize, SMEM_TOTAL);

    normalize_kernel<<<NB, 256>>>(x);
    top2_sym_kernel<<<NCTAS, THREADS, SMEM_TOTAL>>>();
    loss_stage1_kernel<<<RED_BLOCKS, 256>>>();
    loss_stage2_kernel<<<1, 32>>>(out);
}